// round 2
// baseline (speedup 1.0000x reference)
#include <cuda_runtime.h>

#define NPTS   100000
#define BATCH  4096
#define KSEL   10
#define TPB    256
#define RPB    8       // rays per block
#define SUBS   32      // threads per ray
#define TILE   2048    // points per shared tile (32 KB as float4)

__global__ __launch_bounds__(TPB)
void gs_topk_kernel(const float* __restrict__ rays_o,
                    const float* __restrict__ rays_d,
                    const float* __restrict__ xyz,
                    const float* __restrict__ fdc,
                    const float* __restrict__ opac,
                    float* __restrict__ out)
{
    // tile (32 KB) is dead after the scan; merge lists (20 KB) reuse it.
    __shared__ char sbuf[TILE * sizeof(float4)];
    float4* tile = reinterpret_cast<float4*>(sbuf);
    float*  md2  = reinterpret_cast<float*>(sbuf);
    int*    midx = reinterpret_cast<int*>(sbuf + RPB * SUBS * KSEL * sizeof(float));

    __shared__ float scx[RPB], scy[RPB], scz[RPB], sC[RPB];

    const int t       = threadIdx.x;
    const int rl      = t & (RPB - 1);   // ray within block
    const int sub     = t >> 3;          // scanner id within ray (0..31)
    const int rayBase = blockIdx.x * RPB;

    if (t < RPB) {
        int r = rayBase + t;
        float cx = fmaf(3.0f, rays_d[r * 3 + 0], rays_o[r * 3 + 0]);
        float cy = fmaf(3.0f, rays_d[r * 3 + 1], rays_o[r * 3 + 1]);
        float cz = fmaf(3.0f, rays_d[r * 3 + 2], rays_o[r * 3 + 2]);
        scx[t] = cx; scy[t] = cy; scz[t] = cz;
        sC[t]  = cx * cx + cy * cy + cz * cz;
    }
    __syncthreads();

    const float cx = scx[rl], cy = scy[rl], cz = scz[rl], C = sC[rl];

    // Per-thread sorted (ascending) top-K of (q - 2*dot); full d^2 = s + C
    float best[KSEL];
    int   bidx[KSEL];
#pragma unroll
    for (int j = 0; j < KSEL; j++) { best[j] = 3.0e38f; bidx[j] = 0; }
    float thresh = 3.0e38f;   // compare in s-domain: thresh = best[K-1] - C

    for (int base = 0; base < NPTS; base += TILE) {
        int cnt = min(TILE, NPTS - base);
        __syncthreads();
        // Stage tile as (-2x, -2y, -2z, |x|^2): s = 3-FFMA chain
        for (int i = t; i < cnt; i += TPB) {
            float x = xyz[(base + i) * 3 + 0];
            float y = xyz[(base + i) * 3 + 1];
            float z = xyz[(base + i) * 3 + 2];
            float q = fmaf(x, x, fmaf(y, y, z * z));
            tile[i] = make_float4(-2.0f * x, -2.0f * y, -2.0f * z, q);
        }
        __syncthreads();

#pragma unroll 4
        for (int i = sub; i < cnt; i += SUBS) {
            float4 p = tile[i];
            float  s = fmaf(cx, p.x, fmaf(cy, p.y, fmaf(cz, p.z, p.w)));
            if (s < thresh) {
                float v  = s + C;
                int   ii = base + i;
#pragma unroll
                for (int j = 0; j < KSEL; j++) {
                    if (v < best[j]) {
                        float tv = best[j]; int ti = bidx[j];
                        best[j] = v; bidx[j] = ii;
                        v = tv; ii = ti;
                    }
                }
                thresh = best[KSEL - 1] - C;
            }
        }
    }

    __syncthreads();   // everyone done reading tile before aliasing it

    const int lbase = (rl * SUBS + sub) * KSEL;
#pragma unroll
    for (int j = 0; j < KSEL; j++) { md2[lbase + j] = best[j]; midx[lbase + j] = bidx[j]; }

    // Parallel pairwise merge: 32 lists -> 1 sorted top-K per ray
    for (int stride = SUBS / 2; stride >= 1; stride >>= 1) {
        __syncthreads();
        if (sub < stride) {
            int a = (rl * SUBS + sub) * KSEL;
            int b = (rl * SUBS + sub + stride) * KSEL;
            float ov[KSEL]; int oi[KSEL];
            int ia = 0, ib = 0;
#pragma unroll
            for (int k = 0; k < KSEL; k++) {
                float va = md2[a + ia], vb = md2[b + ib];
                if (va <= vb) { ov[k] = va; oi[k] = midx[a + ia]; ia++; }
                else          { ov[k] = vb; oi[k] = midx[b + ib]; ib++; }
            }
#pragma unroll
            for (int k = 0; k < KSEL; k++) { md2[a + k] = ov[k]; midx[a + k] = oi[k]; }
        }
    }
    __syncthreads();

    // Epilogue: one thread per ray
    if (t < RPB) {
        int a = (t * SUBS) * KSEL;
        float wsum = 0.f, r0 = 0.f, g0 = 0.f, b0 = 0.f;
#pragma unroll
        for (int k = 0; k < KSEL; k++) {
            float d2 = md2[a + k];
            int   ii = midx[a + k];
            float d  = sqrtf(fmaxf(d2, 0.0f));
            float op = 1.0f / (1.0f + expf(-opac[ii]));
            float w  = expf(-0.1f * d) * op;
            wsum += w;
            float c0 = 1.0f / (1.0f + expf(-fdc[ii * 3 + 0]));
            float c1 = 1.0f / (1.0f + expf(-fdc[ii * 3 + 1]));
            float c2 = 1.0f / (1.0f + expf(-fdc[ii * 3 + 2]));
            r0 = fmaf(w, c0, r0);
            g0 = fmaf(w, c1, g0);
            b0 = fmaf(w, c2, b0);
        }
        float inv = 1.0f / (wsum + 1e-8f);
        int ray = rayBase + t;
        out[ray * 3 + 0] = r0 * inv;
        out[ray * 3 + 1] = g0 * inv;
        out[ray * 3 + 2] = b0 * inv;
    }
}

extern "C" void kernel_launch(void* const* d_in, const int* in_sizes, int n_in,
                              void* d_out, int out_size)
{
    const float* rays_o = (const float*)d_in[0];
    const float* rays_d = (const float*)d_in[1];
    const float* xyz    = (const float*)d_in[2];
    const float* fdc    = (const float*)d_in[3];
    const float* opac   = (const float*)d_in[4];
    float* out = (float*)d_out;

    gs_topk_kernel<<<BATCH / RPB, TPB>>>(rays_o, rays_d, xyz, fdc, opac, out);
}

// round 3
// speedup vs baseline: 1.3778x; 1.3778x over previous
#include <cuda_runtime.h>

#define NPTS   100000
#define BATCH  4096
#define KSEL   10
#define TPB    512
#define RPB    16      // rays per block
#define SUBS   32      // threads per ray
#define TILE   2048    // points per shared tile (32 KB as float4)

#define MERGE_F (RPB * SUBS * KSEL)   // 5120 floats

__global__ __launch_bounds__(TPB, 2)
void gs_topk_kernel(const float* __restrict__ rays_o,
                    const float* __restrict__ rays_d,
                    const float* __restrict__ xyz,
                    const float* __restrict__ fdc,
                    const float* __restrict__ opac,
                    float* __restrict__ out)
{
    // Union: tile (32 KB) for the scan, then merge lists (40 KB) afterwards.
    __shared__ char sbuf[MERGE_F * 8];   // 40 KB >= TILE*16
    float4* tile = reinterpret_cast<float4*>(sbuf);
    float*  md2  = reinterpret_cast<float*>(sbuf);
    int*    midx = reinterpret_cast<int*>(sbuf + MERGE_F * sizeof(float));

    __shared__ float scx[RPB], scy[RPB], scz[RPB], sC[RPB];
    __shared__ float sT[RPB];            // shared per-ray prune threshold (s-domain)
    volatile float* sTv = sT;

    const int t       = threadIdx.x;
    const int rl      = t & (RPB - 1);   // ray within block
    const int sub     = t >> 4;          // scanner id within ray (0..31)
    const int rayBase = blockIdx.x * RPB;

    if (t < RPB) {
        int r = rayBase + t;
        float cx = fmaf(3.0f, rays_d[r * 3 + 0], rays_o[r * 3 + 0]);
        float cy = fmaf(3.0f, rays_d[r * 3 + 1], rays_o[r * 3 + 1]);
        float cz = fmaf(3.0f, rays_d[r * 3 + 2], rays_o[r * 3 + 2]);
        scx[t] = cx; scy[t] = cy; scz[t] = cz;
        sC[t]  = cx * cx + cy * cy + cz * cz;
        sT[t]  = 3.0e38f;
    }
    __syncthreads();

    const float cx = scx[rl], cy = scy[rl], cz = scz[rl], C = sC[rl];

    // Per-thread sorted (ascending) top-K in s-domain (s = d^2 - C)
    float best[KSEL];
    int   bidx[KSEL];
#pragma unroll
    for (int j = 0; j < KSEL; j++) { best[j] = 3.0e38f; bidx[j] = 0; }
    float tloc = 3.0e38f;                // own best[K-1]

    for (int base = 0; base < NPTS; base += TILE) {
        int cnt = min(TILE, NPTS - base);
        __syncthreads();
        // Stage tile as (-2x, -2y, -2z, |x|^2): s = 3-FFMA chain
        for (int i = t; i < cnt; i += TPB) {
            float x = xyz[(base + i) * 3 + 0];
            float y = xyz[(base + i) * 3 + 1];
            float z = xyz[(base + i) * 3 + 2];
            float q = fmaf(x, x, fmaf(y, y, z * z));
            tile[i] = make_float4(-2.0f * x, -2.0f * y, -2.0f * z, q);
        }
        __syncthreads();

        int i = sub;
        for (; i + 3 * SUBS < cnt; i += 4 * SUBS) {
            float Tl = fminf(sTv[rl], tloc);   // refresh shared threshold per chunk
#pragma unroll
            for (int u = 0; u < 4; u++) {
                float4 p = tile[i + u * SUBS];
                float  s = fmaf(cx, p.x, fmaf(cy, p.y, fmaf(cz, p.z, p.w)));
                if (s < Tl) {
                    float v  = s;
                    int   ii = base + i + u * SUBS;
#pragma unroll
                    for (int j = 0; j < KSEL; j++) {
                        if (v < best[j]) {
                            float tv = best[j]; int ti = bidx[j];
                            best[j] = v; bidx[j] = ii;
                            v = tv; ii = ti;
                        }
                    }
                    tloc = best[KSEL - 1];
                    Tl = fminf(Tl, tloc);
                    if (tloc < sTv[rl]) sTv[rl] = tloc;   // benign race: any value is a valid upper bound
                }
            }
        }
        for (; i < cnt; i += SUBS) {          // tail
            float Tl = fminf(sTv[rl], tloc);
            float4 p = tile[i];
            float  s = fmaf(cx, p.x, fmaf(cy, p.y, fmaf(cz, p.z, p.w)));
            if (s < Tl) {
                float v = s; int ii = base + i;
#pragma unroll
                for (int j = 0; j < KSEL; j++) {
                    if (v < best[j]) {
                        float tv = best[j]; int ti = bidx[j];
                        best[j] = v; bidx[j] = ii;
                        v = tv; ii = ti;
                    }
                }
                tloc = best[KSEL - 1];
                if (tloc < sTv[rl]) sTv[rl] = tloc;
            }
        }
    }

    __syncthreads();   // tile no longer needed; alias as merge arrays

    const int lbase = (rl * SUBS + sub) * KSEL;
#pragma unroll
    for (int j = 0; j < KSEL; j++) {
        md2[lbase + j]  = best[j] + C;   // back to d^2 domain (sentinels stay huge)
        midx[lbase + j] = bidx[j];
    }

    // Parallel pairwise merge: 32 sorted lists -> 1 sorted top-K per ray
    for (int stride = SUBS / 2; stride >= 1; stride >>= 1) {
        __syncthreads();
        if (sub < stride) {
            int a = (rl * SUBS + sub) * KSEL;
            int b = (rl * SUBS + sub + stride) * KSEL;
            float ov[KSEL]; int oi[KSEL];
            int ia = 0, ib = 0;
#pragma unroll
            for (int k = 0; k < KSEL; k++) {
                float va = md2[a + ia], vb = md2[b + ib];
                if (va <= vb) { ov[k] = va; oi[k] = midx[a + ia]; ia++; }
                else          { ov[k] = vb; oi[k] = midx[b + ib]; ib++; }
            }
#pragma unroll
            for (int k = 0; k < KSEL; k++) { md2[a + k] = ov[k]; midx[a + k] = oi[k]; }
        }
    }
    __syncthreads();

    // Epilogue: one thread per ray
    if (t < RPB) {
        int a = (t * SUBS) * KSEL;
        float wsum = 0.f, r0 = 0.f, g0 = 0.f, b0 = 0.f;
#pragma unroll
        for (int k = 0; k < KSEL; k++) {
            float d2 = md2[a + k];
            int   ii = midx[a + k];
            float d  = sqrtf(fmaxf(d2, 0.0f));
            float op = 1.0f / (1.0f + expf(-opac[ii]));
            float w  = expf(-0.1f * d) * op;
            wsum += w;
            float c0 = 1.0f / (1.0f + expf(-fdc[ii * 3 + 0]));
            float c1 = 1.0f / (1.0f + expf(-fdc[ii * 3 + 1]));
            float c2 = 1.0f / (1.0f + expf(-fdc[ii * 3 + 2]));
            r0 = fmaf(w, c0, r0);
            g0 = fmaf(w, c1, g0);
            b0 = fmaf(w, c2, b0);
        }
        float inv = 1.0f / (wsum + 1e-8f);
        int ray = rayBase + t;
        out[ray * 3 + 0] = r0 * inv;
        out[ray * 3 + 1] = g0 * inv;
        out[ray * 3 + 2] = b0 * inv;
    }
}

extern "C" void kernel_launch(void* const* d_in, const int* in_sizes, int n_in,
                              void* d_out, int out_size)
{
    const float* rays_o = (const float*)d_in[0];
    const float* rays_d = (const float*)d_in[1];
    const float* xyz    = (const float*)d_in[2];
    const float* fdc    = (const float*)d_in[3];
    const float* opac   = (const float*)d_in[4];
    float* out = (float*)d_out;

    gs_topk_kernel<<<BATCH / RPB, TPB>>>(rays_o, rays_d, xyz, fdc, opac, out);
}

// round 4
// speedup vs baseline: 1.4693x; 1.0664x over previous
#include <cuda_runtime.h>

#define NPTS   100000
#define BATCH  4096
#define KSEL   10
#define TPB    128
#define RPB    4       // rays per block
#define SUBS   32      // lanes per ray
#define GRID   (BATCH / RPB)   // 1024 blocks
#define UNR    8

__device__ float4 g_packed[NPTS];   // (-2x, -2y, -2z, |x|^2)

__global__ __launch_bounds__(256)
void pack_kernel(const float* __restrict__ xyz)
{
    int i = blockIdx.x * 256 + threadIdx.x;
    if (i < NPTS) {
        float x = xyz[i * 3 + 0];
        float y = xyz[i * 3 + 1];
        float z = xyz[i * 3 + 2];
        float q = fmaf(x, x, fmaf(y, y, z * z));
        g_packed[i] = make_float4(-2.0f * x, -2.0f * y, -2.0f * z, q);
    }
}

__global__ __launch_bounds__(TPB, 8)
void gs_topk_kernel(const float* __restrict__ rays_o,
                    const float* __restrict__ rays_d,
                    const float* __restrict__ fdc,
                    const float* __restrict__ opac,
                    float* __restrict__ out)
{
    __shared__ float md2 [RPB * SUBS * KSEL];   // 5.1 KB
    __shared__ int   midx[RPB * SUBS * KSEL];   // 5.1 KB
    __shared__ float sT[RPB];                   // shared per-ray prune threshold
    volatile float* sTv = sT;

    const int t       = threadIdx.x;
    const int rl      = t & (RPB - 1);          // ray within block
    const int sub     = t >> 2;                 // 0..31
    const int rayBase = blockIdx.x * RPB;

    float cx, cy, cz, C;
    {
        int r = rayBase + rl;
        cx = fmaf(3.0f, rays_d[r * 3 + 0], rays_o[r * 3 + 0]);
        cy = fmaf(3.0f, rays_d[r * 3 + 1], rays_o[r * 3 + 1]);
        cz = fmaf(3.0f, rays_d[r * 3 + 2], rays_o[r * 3 + 2]);
        C  = cx * cx + cy * cy + cz * cz;
    }
    if (t < RPB) sT[t] = 3.0e38f;
    __syncthreads();

    // Per-lane sorted (ascending) top-K in s-domain (s = d^2 - C)
    float best[KSEL];
    int   bidx[KSEL];
#pragma unroll
    for (int j = 0; j < KSEL; j++) { best[j] = 3.0e38f; bidx[j] = 0; }
    float tloc = 3.0e38f;

    const float4* p = g_packed + sub;
    int pbase = sub;

    const int NCHUNK = (NPTS / SUBS) / UNR;       // 390
#pragma unroll 1
    for (int c = 0; c < NCHUNK; c++) {
        float Tl = fminf(sTv[rl], tloc);
        float s[UNR];
#pragma unroll
        for (int u = 0; u < UNR; u++) {
            float4 q = p[u * SUBS];
            s[u] = fmaf(cx, q.x, fmaf(cy, q.y, fmaf(cz, q.z, q.w)));
        }
        float m01 = fminf(s[0], s[1]), m23 = fminf(s[2], s[3]);
        float m45 = fminf(s[4], s[5]), m67 = fminf(s[6], s[7]);
        float m = fminf(fminf(m01, m23), fminf(m45, m67));
        if (m < Tl) {
#pragma unroll
            for (int u = 0; u < UNR; u++) {
                if (s[u] < fminf(Tl, tloc)) {
                    float v  = s[u];
                    int   ii = pbase + u * SUBS;
#pragma unroll
                    for (int j = 0; j < KSEL; j++) {
                        if (v < best[j]) {
                            float tv = best[j]; int ti = bidx[j];
                            best[j] = v; bidx[j] = ii;
                            v = tv; ii = ti;
                        }
                    }
                    tloc = best[KSEL - 1];
                }
            }
            if (tloc < sTv[rl]) sTv[rl] = tloc;   // benign race: any value is a valid bound
        }
        p     += UNR * SUBS;
        pbase += UNR * SUBS;
    }
    // Tail: 5 points per lane
#pragma unroll 1
    for (int k = NCHUNK * UNR * SUBS + sub; k < NPTS; k += SUBS) {
        float4 q = g_packed[k];
        float  s = fmaf(cx, q.x, fmaf(cy, q.y, fmaf(cz, q.z, q.w)));
        if (s < fminf(sTv[rl], tloc)) {
            float v = s; int ii = k;
#pragma unroll
            for (int j = 0; j < KSEL; j++) {
                if (v < best[j]) {
                    float tv = best[j]; int ti = bidx[j];
                    best[j] = v; bidx[j] = ii;
                    v = tv; ii = ti;
                }
            }
            tloc = best[KSEL - 1];
            if (tloc < sTv[rl]) sTv[rl] = tloc;
        }
    }

    const int lbase = (rl * SUBS + sub) * KSEL;
#pragma unroll
    for (int j = 0; j < KSEL; j++) {
        md2[lbase + j]  = best[j] + C;            // back to d^2 domain
        midx[lbase + j] = bidx[j];
    }

    // Parallel pairwise merge: 32 sorted lists -> 1 per ray
    for (int stride = SUBS / 2; stride >= 1; stride >>= 1) {
        __syncthreads();
        if (sub < stride) {
            int a = (rl * SUBS + sub) * KSEL;
            int b = (rl * SUBS + sub + stride) * KSEL;
            float ov[KSEL]; int oi[KSEL];
            int ia = 0, ib = 0;
#pragma unroll
            for (int k = 0; k < KSEL; k++) {
                float va = md2[a + ia], vb = md2[b + ib];
                if (va <= vb) { ov[k] = va; oi[k] = midx[a + ia]; ia++; }
                else          { ov[k] = vb; oi[k] = midx[b + ib]; ib++; }
            }
#pragma unroll
            for (int k = 0; k < KSEL; k++) { md2[a + k] = ov[k]; midx[a + k] = oi[k]; }
        }
    }
    __syncthreads();

    // Epilogue: one thread per ray
    if (t < RPB) {
        int a = (t * SUBS) * KSEL;
        float wsum = 0.f, r0 = 0.f, g0 = 0.f, b0 = 0.f;
#pragma unroll
        for (int k = 0; k < KSEL; k++) {
            float d2 = md2[a + k];
            int   ii = midx[a + k];
            float d  = sqrtf(fmaxf(d2, 0.0f));
            float op = 1.0f / (1.0f + expf(-opac[ii]));
            float w  = expf(-0.1f * d) * op;
            wsum += w;
            float c0 = 1.0f / (1.0f + expf(-fdc[ii * 3 + 0]));
            float c1 = 1.0f / (1.0f + expf(-fdc[ii * 3 + 1]));
            float c2 = 1.0f / (1.0f + expf(-fdc[ii * 3 + 2]));
            r0 = fmaf(w, c0, r0);
            g0 = fmaf(w, c1, g0);
            b0 = fmaf(w, c2, b0);
        }
        float inv = 1.0f / (wsum + 1e-8f);
        int ray = rayBase + t;
        out[ray * 3 + 0] = r0 * inv;
        out[ray * 3 + 1] = g0 * inv;
        out[ray * 3 + 2] = b0 * inv;
    }
}

extern "C" void kernel_launch(void* const* d_in, const int* in_sizes, int n_in,
                              void* d_out, int out_size)
{
    const float* rays_o = (const float*)d_in[0];
    const float* rays_d = (const float*)d_in[1];
    const float* xyz    = (const float*)d_in[2];
    const float* fdc    = (const float*)d_in[3];
    const float* opac   = (const float*)d_in[4];
    float* out = (float*)d_out;

    pack_kernel<<<(NPTS + 255) / 256, 256>>>(xyz);
    gs_topk_kernel<<<GRID, TPB>>>(rays_o, rays_d, fdc, opac, out);
}